// round 13
// baseline (speedup 1.0000x reference)
#include <cuda_runtime.h>
#include <cuda_fp16.h>
#include <cstdint>

// ---------------------------------------------------------------------------
// BiLSTM: B=32, T=512, D=512, H=512. out = [B,T,2H] fp32.
// FUSED persistent kernel, 148 CTAs x 512 threads (R12-validated skeleton):
//   Phase A: all CTAs project s-blocks q<20 (both dirs) via tf32 mma.
//   Phase B: CTAs 0-63 scan (32/dir, j-tile 16); CTAs 64-147 stream proj.
// R13: scan epilogue restructured — gate-interleaved W rows put all 4 gates
//   of a cell in ONE thread's fragments; LSTM cell computed in registers;
//   K-split partials summed via named-barrier warp pairs (no block syncs).
// ---------------------------------------------------------------------------

#define B_  32
#define T_  512
#define D_  512
#define H_  512
#define G4  2048
#define NSCAN 64          // scan CTAs (32 per dir)
#define NBDS  32          // barrier arrivals per dir
#define JT    16          // j columns per scan CTA
#define SHW  520          // W smem row stride (fp16)
#define HSTR 264          // h region row stride (fp16)
#define QA   20           // phase-A s-block prefix
#define NQ   128

// Scratch (device globals: allocation-free rule)
__device__ float g_xg[2][T_][G4][B_];        // [dir][t][gate*H+j][b]
__device__ __half g_h[2][2][B_][H_];         // [buf][dir][b][j]
__device__ unsigned g_bar2[2];
__device__ unsigned g_ctrA, g_ctrB;
__device__ unsigned g_done[NQ];

// ---------------------------------------------------------------------------
__device__ __forceinline__ uint32_t f2tf32(float f) {
    uint32_t r;
    asm("cvt.rna.tf32.f32 %0, %1;" : "=r"(r) : "f"(f));
    return r;
}
__device__ __forceinline__ void mma_tf32(float* c, const uint32_t* a, const uint32_t* b) {
    asm volatile(
        "mma.sync.aligned.m16n8k8.row.col.f32.tf32.tf32.f32 "
        "{%0,%1,%2,%3}, {%4,%5,%6,%7}, {%8,%9}, {%0,%1,%2,%3};"
        : "+f"(c[0]), "+f"(c[1]), "+f"(c[2]), "+f"(c[3])
        : "r"(a[0]), "r"(a[1]), "r"(a[2]), "r"(a[3]), "r"(b[0]), "r"(b[1]));
}
__device__ __forceinline__ void mma_f16(float* c, const uint32_t* a, const uint32_t* b) {
    asm volatile(
        "mma.sync.aligned.m16n8k16.row.col.f32.f16.f16.f32 "
        "{%0,%1,%2,%3}, {%4,%5,%6,%7}, {%8,%9}, {%0,%1,%2,%3};"
        : "+f"(c[0]), "+f"(c[1]), "+f"(c[2]), "+f"(c[3])
        : "r"(a[0]), "r"(a[1]), "r"(a[2]), "r"(a[3]), "r"(b[0]), "r"(b[1]));
}
__device__ __forceinline__ void ldmx4(uint32_t* r, uint32_t addr) {
    asm volatile("ldmatrix.sync.aligned.m8n8.x4.shared.b16 {%0,%1,%2,%3}, [%4];"
        : "=r"(r[0]), "=r"(r[1]), "=r"(r[2]), "=r"(r[3]) : "r"(addr));
}
__device__ __forceinline__ void ldmx2(uint32_t* r, uint32_t addr) {
    asm volatile("ldmatrix.sync.aligned.m8n8.x2.shared.b16 {%0,%1}, [%2];"
        : "=r"(r[0]), "=r"(r[1]) : "r"(addr));
}
__device__ __forceinline__ uint32_t smem_u32(const void* p) {
    uint32_t a;
    asm("{ .reg .u64 t; cvta.to.shared.u64 t, %1; cvt.u32.u64 %0, t; }"
        : "=r"(a) : "l"(p));
    return a;
}
__device__ __forceinline__ void cp_async16(uint32_t dst, const void* src) {
    asm volatile("cp.async.cg.shared.global [%0], [%1], 16;" :: "r"(dst), "l"(src));
}
__device__ __forceinline__ uint16_t hfu(__half v) { return __half_as_ushort(v); }
__device__ __forceinline__ void pair_bar(int id) {
    asm volatile("bar.sync %0, 64;" :: "r"(id) : "memory");
}

// fast activations (validated R4/R6-R12)
__device__ __forceinline__ float sigf(float x) {
    return __fdividef(1.f, 1.f + __expf(-x));
}
__device__ __forceinline__ float tanhfast(float x) {
    float ax = fabsf(x);
    float e  = __expf(-2.f * ax);
    float t  = __fdividef(1.f - e, 1.f + e);
    return copysignf(t, x);
}

// ---------------------------------------------------------------------------
// init: zero h (both bufs), counters, flags
// ---------------------------------------------------------------------------
__global__ void init_kernel() {
    int idx = blockIdx.x * blockDim.x + threadIdx.x;
    if (idx < 2) g_bar2[idx] = 0u;
    if (idx == 2) g_ctrA = 0u;
    if (idx == 3) g_ctrB = 0u;
    if (idx >= 4 && idx < 4 + NQ) g_done[idx - 4] = 0u;
    uint4* z = (uint4*)&g_h[0][0][0][0];     // 8192 uint4
    if (idx < 8192) z[idx] = make_uint4(0, 0, 0, 0);
}

// ---------------------------------------------------------------------------
// smem layout (bytes). Proj region (0..34816) overlaps scan W (phases disjoint).
// ---------------------------------------------------------------------------
#define PA_OFF 0                 // proj A_s: 32*136 floats = 17408
#define PB_OFF 17408             // proj B_s: 17408
#define W0_OFF 0                 // scan W: 64*SHW*2 = 66560
#define HP_OFF 66560             // 8 regions * 4224 = 33792
#define PR_OFF 100352            // pair-reduce: 8*32*9*4 = 9216
#define HN_OFF 109568            // 8 warps * 8*8 floats = 2048
#define BC_OFF 111616            // broadcast slot
#define SMEM_TOT 111744

#define SSTR 136
#define KCH  32

// ---------------------------------------------------------------------------
// proj tile (512 threads): 128x128 tf32 tile; 16 warps = 4 mw x 4 nw.
// (validated R12)
// ---------------------------------------------------------------------------
__device__ void proj_tile(char* sm, int xtile, int mtile,
    const float* __restrict__ x,
    const float* __restrict__ Wf, const float* __restrict__ Wb,
    const float* __restrict__ bihf, const float* __restrict__ bhhf,
    const float* __restrict__ bihb, const float* __restrict__ bhhb)
{
    float* A_s = (float*)(sm + PA_OFF);
    float* B_s = (float*)(sm + PB_OFF);

    const int tid  = threadIdx.x;
    const int lane = tid & 31;
    const int wid  = tid >> 5;
    const int mw   = wid & 3;
    const int nw   = wid >> 2;

    const int dir  = mtile >> 4;
    const int mg0  = (mtile & 15) * 128;
    const int t0   = xtile * 4;
    const float* W = dir ? Wb : Wf;

    const int lrow = tid >> 2;
    const int ls2  = (tid & 3) * 2;
    const int bL   = lrow & 31;
    const int dtL  = lrow >> 5;
    const float* Arow = W + (size_t)(mg0 + lrow) * D_;
    const float* Brow = x + ((size_t)bL * T_ + t0 + dtL) * D_;

    float acc[2][4][4];
#pragma unroll
    for (int mi = 0; mi < 2; mi++)
#pragma unroll
        for (int ni = 0; ni < 4; ni++)
#pragma unroll
            for (int q = 0; q < 4; q++) acc[mi][ni][q] = 0.f;

    const int frag_k = lane & 3;
    const int frag_r = lane >> 2;

    for (int c = 0; c < D_ / KCH; c++) {
        const int kc = c * KCH;
#pragma unroll
        for (int it = 0; it < 2; it++) {
            int k0 = (ls2 + it) * 4;
            float4 av = *(const float4*)(Arow + kc + k0);
            float4 bv = *(const float4*)(Brow + kc + k0);
            A_s[(k0 + 0) * SSTR + lrow] = __uint_as_float(f2tf32(av.x));
            A_s[(k0 + 1) * SSTR + lrow] = __uint_as_float(f2tf32(av.y));
            A_s[(k0 + 2) * SSTR + lrow] = __uint_as_float(f2tf32(av.z));
            A_s[(k0 + 3) * SSTR + lrow] = __uint_as_float(f2tf32(av.w));
            B_s[(k0 + 0) * SSTR + lrow] = __uint_as_float(f2tf32(bv.x));
            B_s[(k0 + 1) * SSTR + lrow] = __uint_as_float(f2tf32(bv.y));
            B_s[(k0 + 2) * SSTR + lrow] = __uint_as_float(f2tf32(bv.z));
            B_s[(k0 + 3) * SSTR + lrow] = __uint_as_float(f2tf32(bv.w));
        }
        __syncthreads();

#pragma unroll
        for (int ks = 0; ks < KCH / 8; ks++) {
            const int kb = ks * 8 + frag_k;
            uint32_t afr[2][4], bfr[4][2];
#pragma unroll
            for (int mi = 0; mi < 2; mi++) {
                int m = mw * 32 + mi * 16 + frag_r;
                afr[mi][0] = __float_as_uint(A_s[kb * SSTR + m]);
                afr[mi][1] = __float_as_uint(A_s[kb * SSTR + m + 8]);
                afr[mi][2] = __float_as_uint(A_s[(kb + 4) * SSTR + m]);
                afr[mi][3] = __float_as_uint(A_s[(kb + 4) * SSTR + m + 8]);
            }
#pragma unroll
            for (int ni = 0; ni < 4; ni++) {
                int n = nw * 32 + ni * 8 + frag_r;
                bfr[ni][0] = __float_as_uint(B_s[kb * SSTR + n]);
                bfr[ni][1] = __float_as_uint(B_s[(kb + 4) * SSTR + n]);
            }
#pragma unroll
            for (int mi = 0; mi < 2; mi++)
#pragma unroll
                for (int ni = 0; ni < 4; ni++)
                    mma_tf32(acc[mi][ni], afr[mi], bfr[ni]);
        }
        __syncthreads();
    }

    const int t  = t0 + nw;
    const int bc = 2 * (lane & 3);
#pragma unroll
    for (int mi = 0; mi < 2; mi++) {
        int g0 = mg0 + mw * 32 + mi * 16 + frag_r;
        float bias0 = dir ? (bihb[g0] + bhhb[g0]) : (bihf[g0] + bhhf[g0]);
        float bias1 = dir ? (bihb[g0 + 8] + bhhb[g0 + 8]) : (bihf[g0 + 8] + bhhf[g0 + 8]);
#pragma unroll
        for (int ni = 0; ni < 4; ni++) {
            int b = ni * 8 + bc;
            *(float2*)&g_xg[dir][t][g0][b] =
                make_float2(acc[mi][ni][0] + bias0, acc[mi][ni][1] + bias0);
            *(float2*)&g_xg[dir][t][g0 + 8][b] =
                make_float2(acc[mi][ni][2] + bias1, acc[mi][ni][3] + bias1);
        }
    }
}

// ---------------------------------------------------------------------------
// fused persistent kernel
// ---------------------------------------------------------------------------
__global__ __launch_bounds__(512, 1) void fused_kernel(
    const float* __restrict__ x,
    const int*   __restrict__ lengths,
    const float* __restrict__ Wihf, const float* __restrict__ Whhf,
    const float* __restrict__ bihf, const float* __restrict__ bhhf,
    const float* __restrict__ Wihb, const float* __restrict__ Whhb,
    const float* __restrict__ bihb, const float* __restrict__ bhhb,
    float*       __restrict__ out)
{
    extern __shared__ __align__(16) char sm[];
    int* bcst = (int*)(sm + BC_OFF);
    const int tid  = threadIdx.x;
    const int lane = tid & 31;
    const int wq   = tid >> 5;

    // ================= Phase A: all CTAs project s-blocks q < QA ==========
    for (;;) {
        if (tid == 0) *bcst = (int)atomicAdd(&g_ctrA, 1u);
        __syncthreads();
        int idx = *bcst;
        __syncthreads();
        if (idx >= QA * 32) break;
        int q = idx >> 5, i = idx & 31;
        proj_tile(sm, (i < 16) ? q : (127 - q), i,
                  x, Wihf, Wihb, bihf, bhhf, bihb, bhhb);
        __threadfence();
        __syncthreads();
        if (tid == 0) atomicAdd(&g_done[q], 1u);
    }

    // ================= Phase B workers: remaining proj tiles ==============
    if (blockIdx.x >= NSCAN) {
        for (;;) {
            if (tid == 0) *bcst = (int)atomicAdd(&g_ctrB, 1u);
            __syncthreads();
            int idx = *bcst;
            __syncthreads();
            if (idx >= (NQ - QA) * 32) return;
            int q = QA + (idx >> 5), i = idx & 31;
            proj_tile(sm, (i < 16) ? q : (127 - q), i,
                      x, Wihf, Wihb, bihf, bhhf, bihb, bhhb);
            __threadfence();
            __syncthreads();
            if (tid == 0) atomicAdd(&g_done[q], 1u);
        }
    }

    // ================= Scan CTAs (0..63): 32 per dir, j-tile 16 ===========
    __half* W0_s = (__half*)(sm + W0_OFF);
    float*  PR_s = (float*)(sm + PR_OFF);   // [8 pid][32 lane][9]
    float*  HN_s = (float*)(sm + HN_OFF);   // [8 pid][8 j][8 b]

    const int bx  = blockIdx.x;
    const int dir = bx >> 5;
    const int j0  = (bx & 31) * JT;
    const float* W = dir ? Whhb : Whhf;
    unsigned* bar = &g_bar2[dir];

    __syncthreads();   // phase A used smem as A_s/B_s

    // ---- stage W fp16, GATE-INTERLEAVED rows ----
    // mrow = wm*32 + (gate>>1)*16 + (gate&1)*8 + jl ; j = j0 + wm*8 + jl
#pragma unroll
    for (int i = 0; i < 16; i++) {
        int v = tid + i * 512;              // 0..8191 (64 rows x 128 segs)
        int mrow = v >> 7;
        int seg  = v & 127;
        int wmr  = mrow >> 5;
        int gate = ((mrow >> 4) & 1) * 2 + ((mrow >> 3) & 1);
        int jl   = mrow & 7;
        float4 wv = __ldg((const float4*)(W +
            (size_t)((gate << 9) + j0 + wmr * 8 + jl) * D_) + seg);
        uint32_t pA = (uint32_t)hfu(__float2half_rn(wv.x)) |
                      ((uint32_t)hfu(__float2half_rn(wv.y)) << 16);
        uint32_t pB = (uint32_t)hfu(__float2half_rn(wv.z)) |
                      ((uint32_t)hfu(__float2half_rn(wv.w)) << 16);
        *(uint2*)((char*)W0_s + (mrow * SHW + seg * 4) * 2) = make_uint2(pA, pB);
    }
    __syncthreads();

    // warp decomposition: kw(2) x wm(2) x wn(4); 2 m16-tiles per warp
    const int kw = wq >> 3;
    const int wm = (wq >> 2) & 1;
    const int wn = wq & 3;
    const int pid = wq & 7;                 // pair id (kw partner shares pid)
    const int l8 = lane & 7, sel = lane >> 3;
    const uint32_t w0b = smem_u32(W0_s);
    uint32_t aoffs[2];
#pragma unroll
    for (int mt = 0; mt < 2; mt++)
        aoffs[mt] = w0b +
            (uint32_t)((wm * 32 + mt * 16 + ((sel & 1) ? 8 : 0) + l8) * SHW
                       + ((sel >> 1) ? 8 : 0) + kw * 256) * 2;
    const uint32_t hreg = smem_u32(sm + HP_OFF) + (uint32_t)(kw * 4 + wn) * 4224;
    const uint32_t boff = hreg + (uint32_t)(l8 * HSTR + ((sel & 1) ? 8 : 0)) * 2;

    // cell identity (kw==0 threads): j = j0 + wm*8 + r ; b pair = wn*8+2cp
    const int fr = lane >> 2;               // r
    const int fc = lane & 3;                // cp
    const int jj = j0 + wm * 8 + fr;
    const int b0 = wn * 8 + 2 * fc;
    const int lenA = __ldg(&lengths[b0]);
    const int lenB = __ldg(&lengths[b0 + 1]);
    float cA = 0.f, hA = 0.f, cB = 0.f, hB = 0.f;
    int cur = 0;
    unsigned target = 0;

    for (int s = 0; s < T_; s++) {
        const int t = dir ? (T_ - 1 - s) : s;

        // ---- xg availability gate (once per 4 steps) ----
        if ((s & 3) == 0) {
            if (tid == 0) {
                const unsigned q = (unsigned)(s >> 2);
                while (__ldcg((const unsigned*)&g_done[q]) < 32u) { }
            }
            __syncthreads();
        }

        // ---- prefetch xg BEFORE barrier (kw0 threads; 4 float2) ----
        float2 xi2, xf2, xg2, xo2;
        if (kw == 0) {
            const float* xgp = &g_xg[dir][t][0][0];
            xi2 = *(const float2*)(xgp + (((0 << 9) + jj) << 5) + b0);
            xf2 = *(const float2*)(xgp + (((1 << 9) + jj) << 5) + b0);
            xg2 = *(const float2*)(xgp + (((2 << 9) + jj) << 5) + b0);
            xo2 = *(const float2*)(xgp + (((3 << 9) + jj) << 5) + b0);
        }

        // ---- per-dir grid barrier ----
        target += NBDS;
        __syncthreads();
        if (tid == 0) {
            atomicAdd(bar, 1u);
            while (*(volatile unsigned*)bar < target) { }
            __threadfence();
        }
        __syncthreads();

        // ---- stage h region (kw,wn): 8 batches x 256 k fp16 (4 KB) ----
#pragma unroll
        for (int i = 0; i < 8; i++) {
            const void* src = (const char*)&g_h[cur][dir][wn * 8 + i][kw * 256] + lane * 16;
            cp_async16(hreg + (uint32_t)i * (HSTR * 2) + (uint32_t)lane * 16, src);
        }
        asm volatile("cp.async.commit_group;");
        asm volatile("cp.async.wait_group 0;" ::: "memory");
        __syncwarp();

        // ---- mainloop: 16 k16-steps, 2 m-tiles (gate-interleaved) ----
        float c0[4] = {0.f, 0.f, 0.f, 0.f};
        float c1[4] = {0.f, 0.f, 0.f, 0.f};
#pragma unroll
        for (int ks = 0; ks < 16; ks++) {
            uint32_t bf[2], a0[4], a1[4];
            ldmx2(bf, boff + ks * 32);
            ldmx4(a0, aoffs[0] + ks * 32);
            ldmx4(a1, aoffs[1] + ks * 32);
            mma_f16(c0, a0, bf);
            mma_f16(c1, a1, bf);
        }

        // ---- pairwise K reduction: kw1 -> smem, named bar, kw0 sums ----
        if (kw == 1) {
            float* dst = PR_s + (pid * 32 + lane) * 9;
            dst[0] = c0[0]; dst[1] = c0[1]; dst[2] = c0[2]; dst[3] = c0[3];
            dst[4] = c1[0]; dst[5] = c1[1]; dst[6] = c1[2]; dst[7] = c1[3];
        }
        pair_bar(pid + 1);
        if (kw == 0) {
            const float* src = PR_s + (pid * 32 + lane) * 9;
            c0[0] += src[0]; c0[1] += src[1]; c0[2] += src[2]; c0[3] += src[3];
            c1[0] += src[4]; c1[1] += src[5]; c1[2] += src[6]; c1[3] += src[7];

            // ---- LSTM cells IN REGISTERS: gates i=c0[0/1], f=c0[2/3],
            //      g=c1[0/1], o=c1[2/3] for (jj, b0) and (jj, b0+1) ----
            {
                float ig = sigf(c0[0] + xi2.x), fg = sigf(c0[2] + xf2.x);
                float gg = tanhfast(c1[0] + xg2.x), og = sigf(c1[2] + xo2.x);
                float cn = fg * cA + ig * gg;
                float hn = og * tanhfast(cn);
                if (t < lenA) { cA = cn; hA = hn; }
            }
            {
                float ig = sigf(c0[1] + xi2.y), fg = sigf(c0[3] + xf2.y);
                float gg = tanhfast(c1[1] + xg2.y), og = sigf(c1[3] + xo2.y);
                float cn = fg * cB + ig * gg;
                float hn = og * tanhfast(cn);
                if (t < lenB) { cB = cn; hB = hn; }
            }

            // ---- warp-local h tile [pid][j(8)][b(8)] ----
            float* hn_t = HN_s + (pid * 64) + fr * 8 + 2 * fc;
            hn_t[0] = hA; hn_t[1] = hB;
            __syncwarp();

            // ---- lanes 0..7: coalesced stores (g_h fp16 row + out fp32) ----
            if (lane < 8) {
                const float* row = HN_s + pid * 64;
                float v0 = row[0 * 8 + lane], v1 = row[1 * 8 + lane];
                float v2 = row[2 * 8 + lane], v3 = row[3 * 8 + lane];
                float v4 = row[4 * 8 + lane], v5 = row[5 * 8 + lane];
                float v6 = row[6 * 8 + lane], v7 = row[7 * 8 + lane];
                int bb = wn * 8 + lane;
                uint4 hw;
                hw.x = (uint32_t)hfu(__float2half_rn(v0)) |
                       ((uint32_t)hfu(__float2half_rn(v1)) << 16);
                hw.y = (uint32_t)hfu(__float2half_rn(v2)) |
                       ((uint32_t)hfu(__float2half_rn(v3)) << 16);
                hw.z = (uint32_t)hfu(__float2half_rn(v4)) |
                       ((uint32_t)hfu(__float2half_rn(v5)) << 16);
                hw.w = (uint32_t)hfu(__float2half_rn(v6)) |
                       ((uint32_t)hfu(__float2half_rn(v7)) << 16);
                __stcg((uint4*)&g_h[cur ^ 1][dir][bb][j0 + wm * 8], hw);
                __threadfence();           // release h before barrier arrive
                float* orow = &out[((size_t)bb * T_ + t) * (2 * H_)
                                   + (dir << 9) + j0 + wm * 8];
                *(float4*)orow       = make_float4(v0, v1, v2, v3);
                *(float4*)(orow + 4) = make_float4(v4, v5, v6, v7);
            }
        }
        cur ^= 1;
    }
}

// ---------------------------------------------------------------------------
extern "C" void kernel_launch(void* const* d_in, const int* in_sizes, int n_in,
                              void* d_out, int out_size)
{
    const float* x      = (const float*)d_in[0];
    const int*   lens   = (const int*)  d_in[1];
    const float* Wihf   = (const float*)d_in[2];
    const float* Whhf   = (const float*)d_in[3];
    const float* bihf   = (const float*)d_in[4];
    const float* bhhf   = (const float*)d_in[5];
    const float* Wihb   = (const float*)d_in[6];
    const float* Whhb   = (const float*)d_in[7];
    const float* bihb   = (const float*)d_in[8];
    const float* bhhb   = (const float*)d_in[9];
    float* out = (float*)d_out;

    cudaFuncSetAttribute(fused_kernel,
                         cudaFuncAttributeMaxDynamicSharedMemorySize, SMEM_TOT);

    init_kernel<<<256, 256>>>();

    fused_kernel<<<148, 512, SMEM_TOT>>>(
        x, lens, Wihf, Whhf, bihf, bhhf, Wihb, Whhb, bihb, bhhb, out);
}

// round 14
// speedup vs baseline: 1.0255x; 1.0255x over previous
#include <cuda_runtime.h>
#include <cuda_fp16.h>
#include <cstdint>

// ---------------------------------------------------------------------------
// BiLSTM: B=32, T=512, D=512, H=512. out = [B,T,2H] fp32.
// FUSED persistent kernel, 148 CTAs x 512 threads:
//   Phase A: all CTAs project s-blocks q<20 (both dirs) via tf32 mma.
//   Phase B: CTAs 0-63 scan (32/dir, j-tile 16); CTAs 64-147 stream proj.
// R14: warp-autonomous scan sync — per-warp ld.acquire polling, per-warp
//   red.release arrivals right after h stores (out stores off critical path),
//   zero block-wide __syncthreads in the step loop, parity-buffered PR.
// ---------------------------------------------------------------------------

#define B_  32
#define T_  512
#define D_  512
#define H_  512
#define G4  2048
#define NSCAN 64          // scan CTAs (32 per dir)
#define ARRV  256         // arrivals per dir per step (8 kw0 warps x 32 CTAs)
#define JT    16          // j columns per scan CTA
#define SHW  520          // W smem row stride (fp16)
#define HSTR 264          // h region row stride (fp16)
#define QA   20           // phase-A s-block prefix
#define NQ   128

// Scratch (device globals: allocation-free rule)
__device__ float g_xg[2][T_][G4][B_];        // [dir][t][gate*H+j][b]
__device__ __half g_h[2][2][B_][H_];         // [buf][dir][b][j]
__device__ unsigned g_bar2[2];
__device__ unsigned g_ctrA, g_ctrB;
__device__ unsigned g_done[NQ];

// ---------------------------------------------------------------------------
__device__ __forceinline__ uint32_t f2tf32(float f) {
    uint32_t r;
    asm("cvt.rna.tf32.f32 %0, %1;" : "=r"(r) : "f"(f));
    return r;
}
__device__ __forceinline__ void mma_tf32(float* c, const uint32_t* a, const uint32_t* b) {
    asm volatile(
        "mma.sync.aligned.m16n8k8.row.col.f32.tf32.tf32.f32 "
        "{%0,%1,%2,%3}, {%4,%5,%6,%7}, {%8,%9}, {%0,%1,%2,%3};"
        : "+f"(c[0]), "+f"(c[1]), "+f"(c[2]), "+f"(c[3])
        : "r"(a[0]), "r"(a[1]), "r"(a[2]), "r"(a[3]), "r"(b[0]), "r"(b[1]));
}
__device__ __forceinline__ void mma_f16(float* c, const uint32_t* a, const uint32_t* b) {
    asm volatile(
        "mma.sync.aligned.m16n8k16.row.col.f32.f16.f16.f32 "
        "{%0,%1,%2,%3}, {%4,%5,%6,%7}, {%8,%9}, {%0,%1,%2,%3};"
        : "+f"(c[0]), "+f"(c[1]), "+f"(c[2]), "+f"(c[3])
        : "r"(a[0]), "r"(a[1]), "r"(a[2]), "r"(a[3]), "r"(b[0]), "r"(b[1]));
}
__device__ __forceinline__ void ldmx4(uint32_t* r, uint32_t addr) {
    asm volatile("ldmatrix.sync.aligned.m8n8.x4.shared.b16 {%0,%1,%2,%3}, [%4];"
        : "=r"(r[0]), "=r"(r[1]), "=r"(r[2]), "=r"(r[3]) : "r"(addr));
}
__device__ __forceinline__ void ldmx2(uint32_t* r, uint32_t addr) {
    asm volatile("ldmatrix.sync.aligned.m8n8.x2.shared.b16 {%0,%1}, [%2];"
        : "=r"(r[0]), "=r"(r[1]) : "r"(addr));
}
__device__ __forceinline__ uint32_t smem_u32(const void* p) {
    uint32_t a;
    asm("{ .reg .u64 t; cvta.to.shared.u64 t, %1; cvt.u32.u64 %0, t; }"
        : "=r"(a) : "l"(p));
    return a;
}
__device__ __forceinline__ void cp_async16(uint32_t dst, const void* src) {
    asm volatile("cp.async.cg.shared.global [%0], [%1], 16;" :: "r"(dst), "l"(src));
}
__device__ __forceinline__ uint16_t hfu(__half v) { return __half_as_ushort(v); }
__device__ __forceinline__ void pair_bar(int id) {
    asm volatile("bar.sync %0, 64;" :: "r"(id) : "memory");
}
__device__ __forceinline__ unsigned ld_acq(const unsigned* p) {
    unsigned v;
    asm volatile("ld.acquire.gpu.u32 %0, [%1];" : "=r"(v) : "l"(p) : "memory");
    return v;
}
__device__ __forceinline__ void red_rel(unsigned* p, unsigned v) {
    asm volatile("red.add.release.gpu.u32 [%0], %1;" :: "l"(p), "r"(v) : "memory");
}

// fast activations (validated R4/R6-R13)
__device__ __forceinline__ float sigf(float x) {
    return __fdividef(1.f, 1.f + __expf(-x));
}
__device__ __forceinline__ float tanhfast(float x) {
    float ax = fabsf(x);
    float e  = __expf(-2.f * ax);
    float t  = __fdividef(1.f - e, 1.f + e);
    return copysignf(t, x);
}

// ---------------------------------------------------------------------------
// init: zero h (both bufs), counters, flags
// ---------------------------------------------------------------------------
__global__ void init_kernel() {
    int idx = blockIdx.x * blockDim.x + threadIdx.x;
    if (idx < 2) g_bar2[idx] = 0u;
    if (idx == 2) g_ctrA = 0u;
    if (idx == 3) g_ctrB = 0u;
    if (idx >= 4 && idx < 4 + NQ) g_done[idx - 4] = 0u;
    uint4* z = (uint4*)&g_h[0][0][0][0];     // 8192 uint4
    if (idx < 8192) z[idx] = make_uint4(0, 0, 0, 0);
}

// ---------------------------------------------------------------------------
// smem layout (bytes). Proj region (0..34816) overlaps scan W (phases disjoint).
// ---------------------------------------------------------------------------
#define PA_OFF 0                 // proj A_s: 32*136 floats = 17408
#define PB_OFF 17408             // proj B_s: 17408
#define W0_OFF 0                 // scan W: 64*SHW*2 = 66560
#define HP_OFF 66560             // 8 regions * 4224 = 33792
#define PR_OFF 100352            // pair-reduce x2 parity: 2*8*32*9*4 = 18432
#define HN_OFF 118784            // 8 warps * 64 floats = 2048
#define BC_OFF 120832            // broadcast slot
#define SMEM_TOT 120960

#define SSTR 136
#define KCH  32

// ---------------------------------------------------------------------------
// proj tile (512 threads): 128x128 tf32 tile; 16 warps = 4 mw x 4 nw.
// (validated R12/R13)
// ---------------------------------------------------------------------------
__device__ void proj_tile(char* sm, int xtile, int mtile,
    const float* __restrict__ x,
    const float* __restrict__ Wf, const float* __restrict__ Wb,
    const float* __restrict__ bihf, const float* __restrict__ bhhf,
    const float* __restrict__ bihb, const float* __restrict__ bhhb)
{
    float* A_s = (float*)(sm + PA_OFF);
    float* B_s = (float*)(sm + PB_OFF);

    const int tid  = threadIdx.x;
    const int lane = tid & 31;
    const int wid  = tid >> 5;
    const int mw   = wid & 3;
    const int nw   = wid >> 2;

    const int dir  = mtile >> 4;
    const int mg0  = (mtile & 15) * 128;
    const int t0   = xtile * 4;
    const float* W = dir ? Wb : Wf;

    const int lrow = tid >> 2;
    const int ls2  = (tid & 3) * 2;
    const int bL   = lrow & 31;
    const int dtL  = lrow >> 5;
    const float* Arow = W + (size_t)(mg0 + lrow) * D_;
    const float* Brow = x + ((size_t)bL * T_ + t0 + dtL) * D_;

    float acc[2][4][4];
#pragma unroll
    for (int mi = 0; mi < 2; mi++)
#pragma unroll
        for (int ni = 0; ni < 4; ni++)
#pragma unroll
            for (int q = 0; q < 4; q++) acc[mi][ni][q] = 0.f;

    const int frag_k = lane & 3;
    const int frag_r = lane >> 2;

    for (int c = 0; c < D_ / KCH; c++) {
        const int kc = c * KCH;
#pragma unroll
        for (int it = 0; it < 2; it++) {
            int k0 = (ls2 + it) * 4;
            float4 av = *(const float4*)(Arow + kc + k0);
            float4 bv = *(const float4*)(Brow + kc + k0);
            A_s[(k0 + 0) * SSTR + lrow] = __uint_as_float(f2tf32(av.x));
            A_s[(k0 + 1) * SSTR + lrow] = __uint_as_float(f2tf32(av.y));
            A_s[(k0 + 2) * SSTR + lrow] = __uint_as_float(f2tf32(av.z));
            A_s[(k0 + 3) * SSTR + lrow] = __uint_as_float(f2tf32(av.w));
            B_s[(k0 + 0) * SSTR + lrow] = __uint_as_float(f2tf32(bv.x));
            B_s[(k0 + 1) * SSTR + lrow] = __uint_as_float(f2tf32(bv.y));
            B_s[(k0 + 2) * SSTR + lrow] = __uint_as_float(f2tf32(bv.z));
            B_s[(k0 + 3) * SSTR + lrow] = __uint_as_float(f2tf32(bv.w));
        }
        __syncthreads();

#pragma unroll
        for (int ks = 0; ks < KCH / 8; ks++) {
            const int kb = ks * 8 + frag_k;
            uint32_t afr[2][4], bfr[4][2];
#pragma unroll
            for (int mi = 0; mi < 2; mi++) {
                int m = mw * 32 + mi * 16 + frag_r;
                afr[mi][0] = __float_as_uint(A_s[kb * SSTR + m]);
                afr[mi][1] = __float_as_uint(A_s[kb * SSTR + m + 8]);
                afr[mi][2] = __float_as_uint(A_s[(kb + 4) * SSTR + m]);
                afr[mi][3] = __float_as_uint(A_s[(kb + 4) * SSTR + m + 8]);
            }
#pragma unroll
            for (int ni = 0; ni < 4; ni++) {
                int n = nw * 32 + ni * 8 + frag_r;
                bfr[ni][0] = __float_as_uint(B_s[kb * SSTR + n]);
                bfr[ni][1] = __float_as_uint(B_s[(kb + 4) * SSTR + n]);
            }
#pragma unroll
            for (int mi = 0; mi < 2; mi++)
#pragma unroll
                for (int ni = 0; ni < 4; ni++)
                    mma_tf32(acc[mi][ni], afr[mi], bfr[ni]);
        }
        __syncthreads();
    }

    const int t  = t0 + nw;
    const int bc = 2 * (lane & 3);
#pragma unroll
    for (int mi = 0; mi < 2; mi++) {
        int g0 = mg0 + mw * 32 + mi * 16 + frag_r;
        float bias0 = dir ? (bihb[g0] + bhhb[g0]) : (bihf[g0] + bhhf[g0]);
        float bias1 = dir ? (bihb[g0 + 8] + bhhb[g0 + 8]) : (bihf[g0 + 8] + bhhf[g0 + 8]);
#pragma unroll
        for (int ni = 0; ni < 4; ni++) {
            int b = ni * 8 + bc;
            *(float2*)&g_xg[dir][t][g0][b] =
                make_float2(acc[mi][ni][0] + bias0, acc[mi][ni][1] + bias0);
            *(float2*)&g_xg[dir][t][g0 + 8][b] =
                make_float2(acc[mi][ni][2] + bias1, acc[mi][ni][3] + bias1);
        }
    }
}

// ---------------------------------------------------------------------------
// fused persistent kernel
// ---------------------------------------------------------------------------
__global__ __launch_bounds__(512, 1) void fused_kernel(
    const float* __restrict__ x,
    const int*   __restrict__ lengths,
    const float* __restrict__ Wihf, const float* __restrict__ Whhf,
    const float* __restrict__ bihf, const float* __restrict__ bhhf,
    const float* __restrict__ Wihb, const float* __restrict__ Whhb,
    const float* __restrict__ bihb, const float* __restrict__ bhhb,
    float*       __restrict__ out)
{
    extern __shared__ __align__(16) char sm[];
    int* bcst = (int*)(sm + BC_OFF);
    const int tid  = threadIdx.x;
    const int lane = tid & 31;
    const int wq   = tid >> 5;

    // ================= Phase A: all CTAs project s-blocks q < QA ==========
    for (;;) {
        if (tid == 0) *bcst = (int)atomicAdd(&g_ctrA, 1u);
        __syncthreads();
        int idx = *bcst;
        __syncthreads();
        if (idx >= QA * 32) break;
        int q = idx >> 5, i = idx & 31;
        proj_tile(sm, (i < 16) ? q : (127 - q), i,
                  x, Wihf, Wihb, bihf, bhhf, bihb, bhhb);
        __threadfence();
        __syncthreads();
        if (tid == 0) atomicAdd(&g_done[q], 1u);
    }

    // ================= Phase B workers: remaining proj tiles ==============
    if (blockIdx.x >= NSCAN) {
        for (;;) {
            if (tid == 0) *bcst = (int)atomicAdd(&g_ctrB, 1u);
            __syncthreads();
            int idx = *bcst;
            __syncthreads();
            if (idx >= (NQ - QA) * 32) return;
            int q = QA + (idx >> 5), i = idx & 31;
            proj_tile(sm, (i < 16) ? q : (127 - q), i,
                      x, Wihf, Wihb, bihf, bhhf, bihb, bhhb);
            __threadfence();
            __syncthreads();
            if (tid == 0) atomicAdd(&g_done[q], 1u);
        }
    }

    // ================= Scan CTAs (0..63): 32 per dir, j-tile 16 ===========
    __half* W0_s = (__half*)(sm + W0_OFF);
    float*  PR_s = (float*)(sm + PR_OFF);   // [2 par][8 pid][32 lane][9]
    float*  HN_s = (float*)(sm + HN_OFF);   // [8 pid][8 j][8 b]

    const int bx  = blockIdx.x;
    const int dir = bx >> 5;
    const int j0  = (bx & 31) * JT;
    const float* W = dir ? Whhb : Whhf;
    unsigned* bar = &g_bar2[dir];

    __syncthreads();   // phase A used smem as A_s/B_s

    // ---- stage W fp16, GATE-INTERLEAVED rows ----
    // mrow = wm*32 + (gate_hi)*16 + (gate_lo)*8 + jl ; j = j0 + wm*8 + jl
#pragma unroll
    for (int i = 0; i < 16; i++) {
        int v = tid + i * 512;              // 0..8191 (64 rows x 128 segs)
        int mrow = v >> 7;
        int seg  = v & 127;
        int wmr  = mrow >> 5;
        int gate = ((mrow >> 4) & 1) * 2 + ((mrow >> 3) & 1);
        int jl   = mrow & 7;
        float4 wv = __ldg((const float4*)(W +
            (size_t)((gate << 9) + j0 + wmr * 8 + jl) * D_) + seg);
        uint32_t pA = (uint32_t)hfu(__float2half_rn(wv.x)) |
                      ((uint32_t)hfu(__float2half_rn(wv.y)) << 16);
        uint32_t pB = (uint32_t)hfu(__float2half_rn(wv.z)) |
                      ((uint32_t)hfu(__float2half_rn(wv.w)) << 16);
        *(uint2*)((char*)W0_s + (mrow * SHW + seg * 4) * 2) = make_uint2(pA, pB);
    }
    __syncthreads();

    // warp decomposition: kw(2) x wm(2) x wn(4); 2 m16-tiles per warp
    const int kw = wq >> 3;
    const int wm = (wq >> 2) & 1;
    const int wn = wq & 3;
    const int pid = wq & 7;                 // pair id (kw partner shares pid)
    const int l8 = lane & 7, sel = lane >> 3;
    const uint32_t w0b = smem_u32(W0_s);
    uint32_t aoffs[2];
#pragma unroll
    for (int mt = 0; mt < 2; mt++)
        aoffs[mt] = w0b +
            (uint32_t)((wm * 32 + mt * 16 + ((sel & 1) ? 8 : 0) + l8) * SHW
                       + ((sel >> 1) ? 8 : 0) + kw * 256) * 2;
    const uint32_t hreg = smem_u32(sm + HP_OFF) + (uint32_t)(kw * 4 + wn) * 4224;
    const uint32_t boff = hreg + (uint32_t)(l8 * HSTR + ((sel & 1) ? 8 : 0)) * 2;

    // cell identity (kw==0 threads): j = j0 + wm*8 + r ; b pair = wn*8+2cp
    const int fr = lane >> 2;
    const int fc = lane & 3;
    const int jj = j0 + wm * 8 + fr;
    const int b0 = wn * 8 + 2 * fc;
    const int lenA = __ldg(&lengths[b0]);
    const int lenB = __ldg(&lengths[b0 + 1]);
    float cA = 0.f, hA = 0.f, cB = 0.f, hB = 0.f;
    int cur = 0;
    unsigned target = 0;       // poll threshold: all h(s-1) arrivals

    for (int s = 0; s < T_; s++) {
        const int t = dir ? (T_ - 1 - s) : s;

        // ---- xg gate + prefetch (kw0 warps only; overlaps peer stalls) ----
        float2 xi2, xf2, xg2, xo2;
        if (kw == 0) {
            if ((s & 3) == 0) {
                const unsigned q = (unsigned)(s >> 2);
                while (ld_acq(&g_done[q]) < 32u) { }
            }
            const float* xgp = &g_xg[dir][t][0][0];
            xi2 = *(const float2*)(xgp + (((0 << 9) + jj) << 5) + b0);
            xf2 = *(const float2*)(xgp + (((1 << 9) + jj) << 5) + b0);
            xg2 = *(const float2*)(xgp + (((2 << 9) + jj) << 5) + b0);
            xo2 = *(const float2*)(xgp + (((3 << 9) + jj) << 5) + b0);
        }

        // ---- per-warp wait: all h(s-1) stored (step 0: target=0, no wait) ----
        while (ld_acq(bar) < target) { }

        // ---- stage h region (kw,wn): 8 batches x 256 k fp16 (4 KB) ----
#pragma unroll
        for (int i = 0; i < 8; i++) {
            const void* src = (const char*)&g_h[cur][dir][wn * 8 + i][kw * 256] + lane * 16;
            cp_async16(hreg + (uint32_t)i * (HSTR * 2) + (uint32_t)lane * 16, src);
        }
        asm volatile("cp.async.commit_group;");
        asm volatile("cp.async.wait_group 0;" ::: "memory");
        __syncwarp();

        // ---- mainloop: 16 k16-steps, 2 m-tiles (gate-interleaved) ----
        float c0[4] = {0.f, 0.f, 0.f, 0.f};
        float c1[4] = {0.f, 0.f, 0.f, 0.f};
#pragma unroll
        for (int ks = 0; ks < 16; ks++) {
            uint32_t bf[2], a0[4], a1[4];
            ldmx2(bf, boff + ks * 32);
            ldmx4(a0, aoffs[0] + ks * 32);
            ldmx4(a1, aoffs[1] + ks * 32);
            mma_f16(c0, a0, bf);
            mma_f16(c1, a1, bf);
        }

        // ---- pairwise K reduction (parity-buffered) ----
        float* PRp = PR_s + (s & 1) * (8 * 32 * 9);
        if (kw == 1) {
            float* dst = PRp + (pid * 32 + lane) * 9;
            dst[0] = c0[0]; dst[1] = c0[1]; dst[2] = c0[2]; dst[3] = c0[3];
            dst[4] = c1[0]; dst[5] = c1[1]; dst[6] = c1[2]; dst[7] = c1[3];
            pair_bar(pid + 1);
        } else {
            pair_bar(pid + 1);
            const float* src = PRp + (pid * 32 + lane) * 9;
            c0[0] += src[0]; c0[1] += src[1]; c0[2] += src[2]; c0[3] += src[3];
            c1[0] += src[4]; c1[1] += src[5]; c1[2] += src[6]; c1[3] += src[7];

            // ---- LSTM cells in registers (i=c0[0/1], f=c0[2/3], g=c1[0/1], o=c1[2/3]) ----
            {
                float ig = sigf(c0[0] + xi2.x), fg = sigf(c0[2] + xf2.x);
                float gg = tanhfast(c1[0] + xg2.x), og = sigf(c1[2] + xo2.x);
                float cn = fg * cA + ig * gg;
                float hn = og * tanhfast(cn);
                if (t < lenA) { cA = cn; hA = hn; }
            }
            {
                float ig = sigf(c0[1] + xi2.y), fg = sigf(c0[3] + xf2.y);
                float gg = tanhfast(c1[1] + xg2.y), og = sigf(c1[3] + xo2.y);
                float cn = fg * cB + ig * gg;
                float hn = og * tanhfast(cn);
                if (t < lenB) { cB = cn; hB = hn; }
            }

            // ---- warp-local h tile [pid][j(8)][b(8)] ----
            float* hn_t = HN_s + (pid * 64) + fr * 8 + 2 * fc;
            hn_t[0] = hA; hn_t[1] = hB;
            __syncwarp();

            // ---- lanes 0..7: h store FIRST, arrive, then out (off-path) ----
            float v0, v1, v2, v3, v4, v5, v6, v7;
            int bb = 0;
            if (lane < 8) {
                const float* row = HN_s + pid * 64;
                v0 = row[0 * 8 + lane]; v1 = row[1 * 8 + lane];
                v2 = row[2 * 8 + lane]; v3 = row[3 * 8 + lane];
                v4 = row[4 * 8 + lane]; v5 = row[5 * 8 + lane];
                v6 = row[6 * 8 + lane]; v7 = row[7 * 8 + lane];
                bb = wn * 8 + lane;
                uint4 hw;
                hw.x = (uint32_t)hfu(__float2half_rn(v0)) |
                       ((uint32_t)hfu(__float2half_rn(v1)) << 16);
                hw.y = (uint32_t)hfu(__float2half_rn(v2)) |
                       ((uint32_t)hfu(__float2half_rn(v3)) << 16);
                hw.z = (uint32_t)hfu(__float2half_rn(v4)) |
                       ((uint32_t)hfu(__float2half_rn(v5)) << 16);
                hw.w = (uint32_t)hfu(__float2half_rn(v6)) |
                       ((uint32_t)hfu(__float2half_rn(v7)) << 16);
                __stcg((uint4*)&g_h[cur ^ 1][dir][bb][j0 + wm * 8], hw);
            }
            __syncwarp();
            if (lane == 0) red_rel(bar, 1u);   // release: h stores visible
            if (lane < 8) {
                float* orow = &out[((size_t)bb * T_ + t) * (2 * H_)
                                   + (dir << 9) + j0 + wm * 8];
                *(float4*)orow       = make_float4(v0, v1, v2, v3);
                *(float4*)(orow + 4) = make_float4(v4, v5, v6, v7);
            }
        }
        target += ARRV;
        cur ^= 1;
    }
}

// ---------------------------------------------------------------------------
extern "C" void kernel_launch(void* const* d_in, const int* in_sizes, int n_in,
                              void* d_out, int out_size)
{
    const float* x      = (const float*)d_in[0];
    const int*   lens   = (const int*)  d_in[1];
    const float* Wihf   = (const float*)d_in[2];
    const float* Whhf   = (const float*)d_in[3];
    const float* bihf   = (const float*)d_in[4];
    const float* bhhf   = (const float*)d_in[5];
    const float* Wihb   = (const float*)d_in[6];
    const float* Whhb   = (const float*)d_in[7];
    const float* bihb   = (const float*)d_in[8];
    const float* bhhb   = (const float*)d_in[9];
    float* out = (float*)d_out;

    cudaFuncSetAttribute(fused_kernel,
                         cudaFuncAttributeMaxDynamicSharedMemorySize, SMEM_TOT);

    init_kernel<<<256, 256>>>();

    fused_kernel<<<148, 512, SMEM_TOT>>>(
        x, lens, Wihf, Whhf, bihf, bhhf, Wihb, Whhb, bihb, bhhb, out);
}

// round 15
// speedup vs baseline: 1.3554x; 1.3216x over previous
#include <cuda_runtime.h>
#include <cuda_fp16.h>
#include <cstdint>

// ---------------------------------------------------------------------------
// BiLSTM: B=32, T=512, D=512, H=512. out = [B,T,2H] fp32.
// FUSED persistent kernel, 148 CTAs x 512 threads:
//   Phase A: all CTAs project s-blocks q<20 (both dirs) via tf32 mma.
//   Phase B: CTAs 0-63 scan (32/dir, j-tile 16); CTAs 64-147 stream proj.
// R15: h exchanged in MMA B-FRAGMENT IMAGE layout (g_hfrag): producer writes
//   one coalesced 1KB block; consumer LDG.64s frags straight into registers.
//   cp.async staging and ALL B-side ldmatrix removed; out stores done by the
//   idle kw1 warps off the critical path.
// ---------------------------------------------------------------------------

#define B_  32
#define T_  512
#define D_  512
#define H_  512
#define G4  2048
#define NSCAN 64          // scan CTAs (32 per dir)
#define ARRV  256         // arrivals per dir per step (8 kw0 warps x 32 CTAs)
#define JT    16          // j columns per scan CTA
#define SHW  520          // W smem row stride (fp16)
#define QA   20           // phase-A s-block prefix
#define NQ   128

// Scratch (device globals: allocation-free rule)
__device__ float g_xg[2][T_][G4][B_];        // [dir][t][gate*H+j][b]
__device__ uint2 g_hfrag[2][2][32][4][32];   // [buf][dir][ks][wn][lane] B-frag
__device__ unsigned g_bar2[2];
__device__ unsigned g_ctrA, g_ctrB;
__device__ unsigned g_done[NQ];

// ---------------------------------------------------------------------------
__device__ __forceinline__ uint32_t f2tf32(float f) {
    uint32_t r;
    asm("cvt.rna.tf32.f32 %0, %1;" : "=r"(r) : "f"(f));
    return r;
}
__device__ __forceinline__ void mma_tf32(float* c, const uint32_t* a, const uint32_t* b) {
    asm volatile(
        "mma.sync.aligned.m16n8k8.row.col.f32.tf32.tf32.f32 "
        "{%0,%1,%2,%3}, {%4,%5,%6,%7}, {%8,%9}, {%0,%1,%2,%3};"
        : "+f"(c[0]), "+f"(c[1]), "+f"(c[2]), "+f"(c[3])
        : "r"(a[0]), "r"(a[1]), "r"(a[2]), "r"(a[3]), "r"(b[0]), "r"(b[1]));
}
__device__ __forceinline__ void mma_f16(float* c, const uint32_t* a, const uint32_t* b) {
    asm volatile(
        "mma.sync.aligned.m16n8k16.row.col.f32.f16.f16.f32 "
        "{%0,%1,%2,%3}, {%4,%5,%6,%7}, {%8,%9}, {%0,%1,%2,%3};"
        : "+f"(c[0]), "+f"(c[1]), "+f"(c[2]), "+f"(c[3])
        : "r"(a[0]), "r"(a[1]), "r"(a[2]), "r"(a[3]), "r"(b[0]), "r"(b[1]));
}
__device__ __forceinline__ void ldmx4(uint32_t* r, uint32_t addr) {
    asm volatile("ldmatrix.sync.aligned.m8n8.x4.shared.b16 {%0,%1,%2,%3}, [%4];"
        : "=r"(r[0]), "=r"(r[1]), "=r"(r[2]), "=r"(r[3]) : "r"(addr));
}
__device__ __forceinline__ uint32_t smem_u32(const void* p) {
    uint32_t a;
    asm("{ .reg .u64 t; cvta.to.shared.u64 t, %1; cvt.u32.u64 %0, t; }"
        : "=r"(a) : "l"(p));
    return a;
}
__device__ __forceinline__ uint16_t hfu(__half v) { return __half_as_ushort(v); }
__device__ __forceinline__ void pair_bar(int id) {
    asm volatile("bar.sync %0, 64;" :: "r"(id) : "memory");
}
__device__ __forceinline__ void kw0_bar() {
    asm volatile("bar.sync 12, 256;" ::: "memory");
}
__device__ __forceinline__ unsigned ld_acq(const unsigned* p) {
    unsigned v;
    asm volatile("ld.acquire.gpu.u32 %0, [%1];" : "=r"(v) : "l"(p) : "memory");
    return v;
}
__device__ __forceinline__ void red_rel(unsigned* p, unsigned v) {
    asm volatile("red.add.release.gpu.u32 [%0], %1;" :: "l"(p), "r"(v) : "memory");
}

// fast activations (validated R4/R6-R14)
__device__ __forceinline__ float sigf(float x) {
    return __fdividef(1.f, 1.f + __expf(-x));
}
__device__ __forceinline__ float tanhfast(float x) {
    float ax = fabsf(x);
    float e  = __expf(-2.f * ax);
    float t  = __fdividef(1.f - e, 1.f + e);
    return copysignf(t, x);
}

// ---------------------------------------------------------------------------
// init: zero h frag buffers, counters, flags
// ---------------------------------------------------------------------------
__global__ void init_kernel() {
    int idx = blockIdx.x * blockDim.x + threadIdx.x;
    if (idx < 2) g_bar2[idx] = 0u;
    if (idx == 2) g_ctrA = 0u;
    if (idx == 3) g_ctrB = 0u;
    if (idx >= 4 && idx < 4 + NQ) g_done[idx - 4] = 0u;
    uint2* z = &g_hfrag[0][0][0][0][0];      // 2*2*32*4*32 = 16384 uint2
    if (idx < 16384) z[idx] = make_uint2(0, 0);
}

// ---------------------------------------------------------------------------
// smem layout (bytes). Proj region (0..34816) overlaps scan W (phases disjoint).
// ---------------------------------------------------------------------------
#define PA_OFF 0                 // proj A_s: 32*136 floats = 17408
#define PB_OFF 17408             // proj B_s: 17408
#define W0_OFF 0                 // scan W: 64*SHW*2 = 66560
#define PR_OFF 66560             // pair-reduce x2 parity: 2*8*32*9*4 = 18432
#define HN2_OFF 84992            // half [16 j][34] = 1088 -> pad 1152
#define HNF_OFF 86144            // float [16 j][34] = 2176
#define BC_OFF 88320             // broadcast slot
#define SMEM_TOT 88448

#define SSTR 136
#define KCH  32

// ---------------------------------------------------------------------------
// proj tile (512 threads): 128x128 tf32 tile; 16 warps = 4 mw x 4 nw.
// (validated R12-R14)
// ---------------------------------------------------------------------------
__device__ void proj_tile(char* sm, int xtile, int mtile,
    const float* __restrict__ x,
    const float* __restrict__ Wf, const float* __restrict__ Wb,
    const float* __restrict__ bihf, const float* __restrict__ bhhf,
    const float* __restrict__ bihb, const float* __restrict__ bhhb)
{
    float* A_s = (float*)(sm + PA_OFF);
    float* B_s = (float*)(sm + PB_OFF);

    const int tid  = threadIdx.x;
    const int lane = tid & 31;
    const int wid  = tid >> 5;
    const int mw   = wid & 3;
    const int nw   = wid >> 2;

    const int dir  = mtile >> 4;
    const int mg0  = (mtile & 15) * 128;
    const int t0   = xtile * 4;
    const float* W = dir ? Wb : Wf;

    const int lrow = tid >> 2;
    const int ls2  = (tid & 3) * 2;
    const int bL   = lrow & 31;
    const int dtL  = lrow >> 5;
    const float* Arow = W + (size_t)(mg0 + lrow) * D_;
    const float* Brow = x + ((size_t)bL * T_ + t0 + dtL) * D_;

    float acc[2][4][4];
#pragma unroll
    for (int mi = 0; mi < 2; mi++)
#pragma unroll
        for (int ni = 0; ni < 4; ni++)
#pragma unroll
            for (int q = 0; q < 4; q++) acc[mi][ni][q] = 0.f;

    const int frag_k = lane & 3;
    const int frag_r = lane >> 2;

    for (int c = 0; c < D_ / KCH; c++) {
        const int kc = c * KCH;
#pragma unroll
        for (int it = 0; it < 2; it++) {
            int k0 = (ls2 + it) * 4;
            float4 av = *(const float4*)(Arow + kc + k0);
            float4 bv = *(const float4*)(Brow + kc + k0);
            A_s[(k0 + 0) * SSTR + lrow] = __uint_as_float(f2tf32(av.x));
            A_s[(k0 + 1) * SSTR + lrow] = __uint_as_float(f2tf32(av.y));
            A_s[(k0 + 2) * SSTR + lrow] = __uint_as_float(f2tf32(av.z));
            A_s[(k0 + 3) * SSTR + lrow] = __uint_as_float(f2tf32(av.w));
            B_s[(k0 + 0) * SSTR + lrow] = __uint_as_float(f2tf32(bv.x));
            B_s[(k0 + 1) * SSTR + lrow] = __uint_as_float(f2tf32(bv.y));
            B_s[(k0 + 2) * SSTR + lrow] = __uint_as_float(f2tf32(bv.z));
            B_s[(k0 + 3) * SSTR + lrow] = __uint_as_float(f2tf32(bv.w));
        }
        __syncthreads();

#pragma unroll
        for (int ks = 0; ks < KCH / 8; ks++) {
            const int kb = ks * 8 + frag_k;
            uint32_t afr[2][4], bfr[4][2];
#pragma unroll
            for (int mi = 0; mi < 2; mi++) {
                int m = mw * 32 + mi * 16 + frag_r;
                afr[mi][0] = __float_as_uint(A_s[kb * SSTR + m]);
                afr[mi][1] = __float_as_uint(A_s[kb * SSTR + m + 8]);
                afr[mi][2] = __float_as_uint(A_s[(kb + 4) * SSTR + m]);
                afr[mi][3] = __float_as_uint(A_s[(kb + 4) * SSTR + m + 8]);
            }
#pragma unroll
            for (int ni = 0; ni < 4; ni++) {
                int n = nw * 32 + ni * 8 + frag_r;
                bfr[ni][0] = __float_as_uint(B_s[kb * SSTR + n]);
                bfr[ni][1] = __float_as_uint(B_s[(kb + 4) * SSTR + n]);
            }
#pragma unroll
            for (int mi = 0; mi < 2; mi++)
#pragma unroll
                for (int ni = 0; ni < 4; ni++)
                    mma_tf32(acc[mi][ni], afr[mi], bfr[ni]);
        }
        __syncthreads();
    }

    const int t  = t0 + nw;
    const int bc = 2 * (lane & 3);
#pragma unroll
    for (int mi = 0; mi < 2; mi++) {
        int g0 = mg0 + mw * 32 + mi * 16 + frag_r;
        float bias0 = dir ? (bihb[g0] + bhhb[g0]) : (bihf[g0] + bhhf[g0]);
        float bias1 = dir ? (bihb[g0 + 8] + bhhb[g0 + 8]) : (bihf[g0 + 8] + bhhf[g0 + 8]);
#pragma unroll
        for (int ni = 0; ni < 4; ni++) {
            int b = ni * 8 + bc;
            *(float2*)&g_xg[dir][t][g0][b] =
                make_float2(acc[mi][ni][0] + bias0, acc[mi][ni][1] + bias0);
            *(float2*)&g_xg[dir][t][g0 + 8][b] =
                make_float2(acc[mi][ni][2] + bias1, acc[mi][ni][3] + bias1);
        }
    }
}

// ---------------------------------------------------------------------------
// fused persistent kernel
// ---------------------------------------------------------------------------
__global__ __launch_bounds__(512, 1) void fused_kernel(
    const float* __restrict__ x,
    const int*   __restrict__ lengths,
    const float* __restrict__ Wihf, const float* __restrict__ Whhf,
    const float* __restrict__ bihf, const float* __restrict__ bhhf,
    const float* __restrict__ Wihb, const float* __restrict__ Whhb,
    const float* __restrict__ bihb, const float* __restrict__ bhhb,
    float*       __restrict__ out)
{
    extern __shared__ __align__(16) char sm[];
    int* bcst = (int*)(sm + BC_OFF);
    const int tid  = threadIdx.x;
    const int lane = tid & 31;
    const int wq   = tid >> 5;

    // ================= Phase A: all CTAs project s-blocks q < QA ==========
    for (;;) {
        if (tid == 0) *bcst = (int)atomicAdd(&g_ctrA, 1u);
        __syncthreads();
        int idx = *bcst;
        __syncthreads();
        if (idx >= QA * 32) break;
        int q = idx >> 5, i = idx & 31;
        proj_tile(sm, (i < 16) ? q : (127 - q), i,
                  x, Wihf, Wihb, bihf, bhhf, bihb, bhhb);
        __threadfence();
        __syncthreads();
        if (tid == 0) atomicAdd(&g_done[q], 1u);
    }

    // ================= Phase B workers: remaining proj tiles ==============
    if (blockIdx.x >= NSCAN) {
        for (;;) {
            if (tid == 0) *bcst = (int)atomicAdd(&g_ctrB, 1u);
            __syncthreads();
            int idx = *bcst;
            __syncthreads();
            if (idx >= (NQ - QA) * 32) return;
            int q = QA + (idx >> 5), i = idx & 31;
            proj_tile(sm, (i < 16) ? q : (127 - q), i,
                      x, Wihf, Wihb, bihf, bhhf, bihb, bhhb);
            __threadfence();
            __syncthreads();
            if (tid == 0) atomicAdd(&g_done[q], 1u);
        }
    }

    // ================= Scan CTAs (0..63): 32 per dir, j-tile 16 ===========
    __half* W0_s  = (__half*)(sm + W0_OFF);
    float*  PR_s  = (float*)(sm + PR_OFF);    // [2 par][8 pid][32 lane][9]
    __half* HN2_s = (__half*)(sm + HN2_OFF);  // [16 j][34]
    float*  HNF_s = (float*)(sm + HNF_OFF);   // [16 j][34]

    const int bx  = blockIdx.x;
    const int dir = bx >> 5;
    const int j0  = (bx & 31) * JT;
    const int ksb = j0 >> 4;                  // this CTA's ks block
    const float* W = dir ? Whhb : Whhf;
    unsigned* bar = &g_bar2[dir];

    __syncthreads();   // phase A used smem as A_s/B_s

    // ---- stage W fp16, GATE-INTERLEAVED rows ----
#pragma unroll
    for (int i = 0; i < 16; i++) {
        int v = tid + i * 512;              // 0..8191 (64 rows x 128 segs)
        int mrow = v >> 7;
        int seg  = v & 127;
        int wmr  = mrow >> 5;
        int gate = ((mrow >> 4) & 1) * 2 + ((mrow >> 3) & 1);
        int jl   = mrow & 7;
        float4 wv = __ldg((const float4*)(W +
            (size_t)((gate << 9) + j0 + wmr * 8 + jl) * D_) + seg);
        uint32_t pA = (uint32_t)hfu(__float2half_rn(wv.x)) |
                      ((uint32_t)hfu(__float2half_rn(wv.y)) << 16);
        uint32_t pB = (uint32_t)hfu(__float2half_rn(wv.z)) |
                      ((uint32_t)hfu(__float2half_rn(wv.w)) << 16);
        *(uint2*)((char*)W0_s + (mrow * SHW + seg * 4) * 2) = make_uint2(pA, pB);
    }
    __syncthreads();

    // warp decomposition: kw(2) x wm(2) x wn(4)
    const int kw = wq >> 3;
    const int wm = (wq >> 2) & 1;
    const int wn = wq & 3;
    const int pid = wq & 7;
    const int l8 = lane & 7, sel = lane >> 3;
    const uint32_t w0b = smem_u32(W0_s);
    uint32_t aoffs[2];
#pragma unroll
    for (int mt = 0; mt < 2; mt++)
        aoffs[mt] = w0b +
            (uint32_t)((wm * 32 + mt * 16 + ((sel & 1) ? 8 : 0) + l8) * SHW
                       + ((sel >> 1) ? 8 : 0) + kw * 256) * 2;

    // consumer B-frag source: g_hfrag[cur][dir][kw*16 + ks][wn][lane]
    const uint2* hf_base0 = &g_hfrag[0][dir][kw * 16][wn][lane];
    const uint2* hf_base1 = &g_hfrag[1][dir][kw * 16][wn][lane];

    // producer store: flat uint32 index ksb*256 + tid (kw0 threads = tid 0..255)
    uint32_t* hp0 = (uint32_t*)&g_hfrag[0][dir][0][0][0] + ksb * 256 + tid;
    uint32_t* hp1 = (uint32_t*)&g_hfrag[1][dir][0][0][0] + ksb * 256 + tid;
    // producer gather from HN2: u = tid: wn_u = u>>6, t_u = (u>>1)&31, r_u = u&1
    const int pk1 = ((tid >> 1) & 3) * 2 + (tid & 1) * 8;   // local j of half 0
    const int pb  = ((tid >> 6) & 3) * 8 + (((tid >> 1) & 31) >> 2);

    // cell identity (kw0 threads): j = j0 + wm*8 + fr ; b pair = wn*8 + 2*fc
    const int fr = lane >> 2;
    const int fc = lane & 3;
    const int jl_cell = wm * 8 + fr;          // local j
    const int jj = j0 + jl_cell;
    const int b0 = wn * 8 + 2 * fc;
    const int lenA = __ldg(&lengths[b0]);
    const int lenB = __ldg(&lengths[b0 + 1]);
    float cA = 0.f, hA = 0.f, cB = 0.f, hB = 0.f;
    int cur = 0;
    unsigned target = 0;

    for (int s = 0; s < T_; s++) {
        const int t = dir ? (T_ - 1 - s) : s;

        // ---- xg gate + prefetch (kw0 warps only) ----
        float2 xi2, xf2, xg2, xo2;
        if (kw == 0) {
            if ((s & 3) == 0) {
                const unsigned q = (unsigned)(s >> 2);
                while (ld_acq(&g_done[q]) < 32u) { }
            }
            const float* xgp = &g_xg[dir][t][0][0];
            xi2 = *(const float2*)(xgp + (((0 << 9) + jj) << 5) + b0);
            xf2 = *(const float2*)(xgp + (((1 << 9) + jj) << 5) + b0);
            xg2 = *(const float2*)(xgp + (((2 << 9) + jj) << 5) + b0);
            xo2 = *(const float2*)(xgp + (((3 << 9) + jj) << 5) + b0);
        }

        // ---- per-warp wait: all h(s-1) frag stores released ----
        while (ld_acq(bar) < target) { }

        // ---- prefetch B frags: 16 independent LDG.64 (L2-hit, coalesced) ----
        const uint2* hfb = cur ? hf_base1 : hf_base0;
        uint2 bfr[16];
#pragma unroll
        for (int ks = 0; ks < 16; ks++)
            bfr[ks] = __ldcg(hfb + ks * 128);     // stride: [ks][4][32]

        // ---- mainloop: 16 k16-steps, A from smem ldsm, B from regs ----
        float c0[4] = {0.f, 0.f, 0.f, 0.f};
        float c1[4] = {0.f, 0.f, 0.f, 0.f};
#pragma unroll
        for (int ks = 0; ks < 16; ks++) {
            uint32_t a0[4], a1[4];
            ldmx4(a0, aoffs[0] + ks * 32);
            ldmx4(a1, aoffs[1] + ks * 32);
            mma_f16(c0, a0, (const uint32_t*)&bfr[ks]);
            mma_f16(c1, a1, (const uint32_t*)&bfr[ks]);
        }

        // ---- pairwise K reduction (parity-buffered) ----
        float* PRp = PR_s + (s & 1) * (8 * 32 * 9);
        if (kw == 1) {
            float* dst = PRp + (pid * 32 + lane) * 9;
            dst[0] = c0[0]; dst[1] = c0[1]; dst[2] = c0[2]; dst[3] = c0[3];
            dst[4] = c1[0]; dst[5] = c1[1]; dst[6] = c1[2]; dst[7] = c1[3];
            pair_bar(pid + 1);
            // out stores happen after the block bar below
        } else {
            pair_bar(pid + 1);
            const float* src = PRp + (pid * 32 + lane) * 9;
            c0[0] += src[0]; c0[1] += src[1]; c0[2] += src[2]; c0[3] += src[3];
            c1[0] += src[4]; c1[1] += src[5]; c1[2] += src[6]; c1[3] += src[7];

            // ---- LSTM cells in registers ----
            {
                float ig = sigf(c0[0] + xi2.x), fg = sigf(c0[2] + xf2.x);
                float gg = tanhfast(c1[0] + xg2.x), og = sigf(c1[2] + xo2.x);
                float cn = fg * cA + ig * gg;
                float hn = og * tanhfast(cn);
                if (t < lenA) { cA = cn; hA = hn; }
            }
            {
                float ig = sigf(c0[1] + xi2.y), fg = sigf(c0[3] + xf2.y);
                float gg = tanhfast(c1[1] + xg2.y), og = sigf(c1[3] + xo2.y);
                float cn = fg * cB + ig * gg;
                float hn = og * tanhfast(cn);
                if (t < lenB) { cB = cn; hB = hn; }
            }

            // ---- publish to block tiles: HN2 (half, frag gather) + HNF (out) ----
            __half2 hh = __floats2half2_rn(hA, hB);
            *(__half2*)&HN2_s[jl_cell * 34 + b0] = hh;
            *(float2*)&HNF_s[jl_cell * 34 + b0] = make_float2(hA, hB);
            kw0_bar();                                  // HN2 complete (256 thr)

            // ---- frag-image store: ONE uint32 per thread, coalesced 1KB ----
            uint32_t w = (uint32_t)hfu(HN2_s[pk1 * 34 + pb]) |
                         ((uint32_t)hfu(HN2_s[(pk1 + 1) * 34 + pb]) << 16);
            uint32_t* hp = cur ? hp0 : hp1;             // write NEXT buffer
            asm volatile("st.global.cg.u32 [%0], %1;" :: "l"(hp), "r"(w) : "memory");
            __syncwarp();
            if (lane == 0) red_rel(bar, 1u);            // release h(s) frags
        }

        // ---- block bar: HNF ready; kw1 does out stores (off critical path) ----
        asm volatile("bar.sync 0, 512;" ::: "memory");
        if (kw == 1) {
            int u2 = tid - 256;                         // 0..255
            int bb = u2 >> 3, jp = (u2 & 7) * 2;
            float2 v = make_float2(HNF_s[jp * 34 + bb], HNF_s[(jp + 1) * 34 + bb]);
            *(float2*)&out[((size_t)bb * T_ + t) * (2 * H_) + (dir << 9) + j0 + jp] = v;
        }

        target += ARRV;
        cur ^= 1;
    }
}

// ---------------------------------------------------------------------------
extern "C" void kernel_launch(void* const* d_in, const int* in_sizes, int n_in,
                              void* d_out, int out_size)
{
    const float* x      = (const float*)d_in[0];
    const int*   lens   = (const int*)  d_in[1];
    const float* Wihf   = (const float*)d_in[2];
    const float* Whhf   = (const float*)d_in[3];
    const float* bihf   = (const float*)d_in[4];
    const float* bhhf   = (const float*)d_in[5];
    const float* Wihb   = (const float*)d_in[6];
    const float* Whhb   = (const float*)d_in[7];
    const float* bihb   = (const float*)d_in[8];
    const float* bhhb   = (const float*)d_in[9];
    float* out = (float*)d_out;

    cudaFuncSetAttribute(fused_kernel,
                         cudaFuncAttributeMaxDynamicSharedMemorySize, SMEM_TOT);

    init_kernel<<<256, 256>>>();

    fused_kernel<<<148, 512, SMEM_TOT>>>(
        x, lens, Wihf, Whhf, bihf, bhhf, Wihb, Whhb, bihb, bhhb, out);
}